// round 11
// baseline (speedup 1.0000x reference)
#include <cuda_runtime.h>
#include <cuda_bf16.h>
#include <cstdint>
#include <math.h>

// EulerRosenbrockModel: B=512, D=256, HID=1024, H_STEP=0.01
// out = v + 1.5 B v,  B = (h/3) J   (dropped 1.5 B^2 v ~ 8e-6 rel)
// SINGLE persistent kernel (128 CTAs, one wave) with software grid barriers.
// Phases: split | L1(split bf16, tanh) | S1(split, z-partials) | reduce1(v) |
//         L2(plain, muls) | S2(plain, z-partials) | reduce2(out).

static constexpr int BATCH = 512;
static constexpr int DIM   = 256;
static constexpr int HID   = 1024;
static constexpr int BD    = BATCH * DIM;
static constexpr int NB    = 128;            // grid size (single wave)

__device__ float g_T   [BATCH * HID];
__device__ float g_V   [BD];
__device__ float g_part[4 * BD];
__device__ __nv_bfloat16 g_ys [BATCH * 2 * DIM];
__device__ __nv_bfloat16 g_W1s[HID   * 2 * DIM];
__device__ __nv_bfloat16 g_W2s[DIM   * 2 * HID];
__device__ __nv_bfloat16 g_Ts [BATCH * 2 * HID];
__device__ __nv_bfloat16 g_Pp [BATCH * HID];
__device__ __nv_bfloat16 g_Vp [BD];

// grid barrier state (replay-safe: cnt self-resets; gen is compared by equality)
__device__ unsigned g_barCnt = 0;
__device__ volatile unsigned g_barGen = 0;

__device__ __forceinline__ void grid_bar() {
    __syncthreads();
    if (threadIdx.x == 0) {
        __threadfence();                       // release my CTA's stores
        unsigned gen = g_barGen;
        if (atomicAdd(&g_barCnt, 1) == NB - 1) {
            g_barCnt = 0;
            __threadfence();                   // cnt reset visible before gen bump
            g_barGen = gen + 1;
        } else {
            while (g_barGen == gen) { __nanosleep(64); }
        }
        __threadfence();                       // acquire
    }
    __syncthreads();
}

// ---------------- low-level helpers ----------------
__device__ __forceinline__ uint32_t smem_u32(const void* p) {
    uint32_t a;
    asm("{ .reg .u64 t; cvta.to.shared.u64 t, %1; cvt.u32.u64 %0, t; }"
        : "=r"(a) : "l"(p));
    return a;
}
__device__ __forceinline__ void cp16(uint32_t dst, const void* src) {
    asm volatile("cp.async.cg.shared.global [%0], [%1], 16;" :: "r"(dst), "l"(src));
}
__device__ __forceinline__ void cp_commit() {
    asm volatile("cp.async.commit_group;" ::: "memory");
}
template<int N>
__device__ __forceinline__ void cp_wait() {
    asm volatile("cp.async.wait_group %0;" :: "n"(N) : "memory");
}
__device__ __forceinline__ void ldm4(uint32_t* r, uint32_t addr) {
    asm volatile("ldmatrix.sync.aligned.m8n8.x4.shared.b16 {%0,%1,%2,%3}, [%4];"
        : "=r"(r[0]), "=r"(r[1]), "=r"(r[2]), "=r"(r[3]) : "r"(addr));
}
__device__ __forceinline__ void mma_bf16(float* d, const uint32_t* a, const uint32_t* b) {
    asm volatile("mma.sync.aligned.m16n8k16.row.col.f32.bf16.bf16.f32 "
        "{%0,%1,%2,%3}, {%4,%5,%6,%7}, {%8,%9}, {%0,%1,%2,%3};"
        : "+f"(d[0]), "+f"(d[1]), "+f"(d[2]), "+f"(d[3])
        : "r"(a[0]), "r"(a[1]), "r"(a[2]), "r"(a[3]), "r"(b[0]), "r"(b[1]));
}
__device__ __forceinline__ void st_split(__nv_bfloat16* Cs, int Kw, int m, int n,
                                         float v0, float v1) {
    __nv_bfloat162 h = __floats2bfloat162_rn(v0, v1);
    float l0 = v0 - __bfloat162float(h.x);
    float l1 = v1 - __bfloat162float(h.y);
    __nv_bfloat162 l = __floats2bfloat162_rn(l0, l1);
    *(__nv_bfloat162*)&Cs[(size_t)m * (2 * Kw) + n]      = h;
    *(__nv_bfloat162*)&Cs[(size_t)m * (2 * Kw) + Kw + n] = l;
}

#define MODE_TANH 0
#define MODE_MULS 1
#define MODE_PART 2

// One 32x64 output tile; 4-stage cp.async ring; one __syncthreads per chunk.
// NREG=3: split precision (12 chunks); NREG=1: plain bf16 (4 chunks).
// MODE_PART writes fp32 to C directly (caller pre-offsets by z).
template<int MODE, int NREG>
__device__ __forceinline__ void gemm_tile(
    uint32_t sb,
    const __nv_bfloat16* __restrict__ A, int lda,
    const __nv_bfloat16* __restrict__ Bw, int ldb, int Ka,
    float* __restrict__ C, __nv_bfloat16* __restrict__ Cs, int Nglob,
    const float* __restrict__ bias, const float* __restrict__ tanhT,
    int m0, int n0, int zoff)
{
    constexpr int CHUNKS = 4 * NREG;
    constexpr int STAGE  = 12288;

    const int tid = threadIdx.x;
    const int wid = tid >> 5;
    const int lid = tid & 31;
    const int wm  = wid >> 2;
    const int wn  = wid & 3;

    __syncthreads();   // previous tile's smem reads are done before we refill

    float acc[2][4];
    #pragma unroll
    for (int g = 0; g < 2; g++)
        #pragma unroll
        for (int q = 0; q < 4; q++) acc[g][q] = 0.0f;

    const int m_l = wm * 16 + ((lid >> 3) & 1) * 8 + (lid & 7);
    const int n_l = wn * 16 + (lid >> 4) * 8 + (lid & 7);
    const int a_so = (lid >> 4);
    const int b_so = ((lid >> 3) & 1);
    const uint32_t ax = (uint32_t)((m_l & 7) << 4);
    const uint32_t bx = (uint32_t)((n_l & 7) << 4);

    auto issue = [&](int cc, int st) {
        const int r  = (NREG == 3) ? (cc >> 2) : 0;
        const int kb = (cc & 3) * 64;
        const int ak = zoff + kb + (r == 2 ? Ka : 0);
        const int bk = zoff + kb + (r == 1 ? Ka : 0);
        const uint32_t ab = sb + st * STAGE;
        const uint32_t bb = ab + 4096;
        #pragma unroll
        for (int t = tid; t < 768; t += 256) {
            const int row = (t & 255) >> 3, seg = t & 7;
            const uint32_t sw = (uint32_t)(seg * 16) ^ (uint32_t)((row & 7) << 4);
            if (t < 256) {
                cp16(ab + row * 128 + sw,
                     A + (size_t)(m0 + row) * lda + ak + seg * 8);
            } else {
                const int rr = t >= 512 ? row + 32 : row;
                cp16(bb + rr * 128 + sw,
                     Bw + (size_t)(n0 + rr) * ldb + bk + seg * 8);
            }
        }
    };

    issue(0, 0); cp_commit();
    issue(1, 1); cp_commit();
    if (CHUNKS > 2) { issue(2, 2); cp_commit(); }

    #pragma unroll 1
    for (int c = 0; c < CHUNKS; c++) {
        const int rem = CHUNKS - 1 - c;
        if (rem >= 2)      cp_wait<2>();
        else if (rem == 1) cp_wait<1>();
        else               cp_wait<0>();
        __syncthreads();
        if (c + 3 < CHUNKS) { issue(c + 3, (c + 3) & 3); cp_commit(); }

        const uint32_t ab = sb + (c & 3) * STAGE;
        const uint32_t aRow = ab + m_l * 128;
        const uint32_t bRow = ab + 4096 + n_l * 128;
        #pragma unroll
        for (int k = 0; k < 4; k++) {
            uint32_t a0[4], b[4];
            const uint32_t as = (uint32_t)((k * 2 + a_so) * 16) ^ ax;
            const uint32_t bs = (uint32_t)((k * 2 + b_so) * 16) ^ bx;
            ldm4(a0, aRow + as);
            ldm4(b,  bRow + bs);
            mma_bf16(acc[0], a0, b);
            mma_bf16(acc[1], a0, b + 2);
        }
    }

    const int gid  = lid >> 2;
    const int tid4 = lid & 3;
    #pragma unroll
    for (int g = 0; g < 2; g++) {
        const int m = m0 + wm * 16 + gid;
        const int n = n0 + wn * 16 + g * 8 + tid4 * 2;
        const float* ac = acc[g];
        if (MODE == MODE_TANH) {
            const float b0v = bias[n], b1v = bias[n + 1];
            float v00 = tanhf(ac[0] + b0v), v01 = tanhf(ac[1] + b1v);
            float v10 = tanhf(ac[2] + b0v), v11 = tanhf(ac[3] + b1v);
            *(float2*)&C[(size_t)m * Nglob + n]       = make_float2(v00, v01);
            *(float2*)&C[(size_t)(m + 8) * Nglob + n] = make_float2(v10, v11);
            st_split(Cs, Nglob, m,     n, v00, v01);
            st_split(Cs, Nglob, m + 8, n, v10, v11);
        } else if (MODE == MODE_MULS) {
            float2 t0 = *(const float2*)&tanhT[(size_t)m * Nglob + n];
            float2 t1 = *(const float2*)&tanhT[(size_t)(m + 8) * Nglob + n];
            __nv_bfloat162 h0 = __floats2bfloat162_rn(
                ac[0] * (1.0f - t0.x * t0.x), ac[1] * (1.0f - t0.y * t0.y));
            __nv_bfloat162 h1 = __floats2bfloat162_rn(
                ac[2] * (1.0f - t1.x * t1.x), ac[3] * (1.0f - t1.y * t1.y));
            *(__nv_bfloat162*)&Cs[(size_t)m * Nglob + n]       = h0;
            *(__nv_bfloat162*)&Cs[(size_t)(m + 8) * Nglob + n] = h1;
        } else {
            *(float2*)&C[(size_t)m * Nglob + n]       = make_float2(ac[0], ac[1]);
            *(float2*)&C[(size_t)(m + 8) * Nglob + n] = make_float2(ac[2], ac[3]);
        }
    }
}

// -------------------- the single persistent kernel --------------------
__global__ void __launch_bounds__(256)
fused_all(const float* __restrict__ y,  const float* __restrict__ W1,
          const float* __restrict__ b1, const float* __restrict__ W2,
          const float* __restrict__ b2, float* __restrict__ out)
{
    __shared__ __align__(1024) char smem[49152];
    const uint32_t sb = smem_u32(smem);
    const int cta = blockIdx.x;
    const int tid = threadIdx.x;
    const float c3 = 0.01f / 3.0f;

    // ---- phase 0: split y, W1, W2 into [hi|lo] bf16 panels (640 units) ----
    #pragma unroll 1
    for (int i = 0; i < 5; i++) {
        int b = cta + i * NB;
        const float* in;
        __nv_bfloat16* outs;
        int K;
        if (b < 128)      { in = y;  outs = g_ys;  K = DIM; }
        else if (b < 384) { in = W1; outs = g_W1s; K = DIM;  b -= 128; }
        else              { in = W2; outs = g_W2s; K = HID;  b -= 384; }
        const int e4 = (b * 256 + tid) * 4;
        const int row = e4 / K, k = e4 % K;
        float4 v = *(const float4*)&in[e4];
        __nv_bfloat162 h0 = __floats2bfloat162_rn(v.x, v.y);
        __nv_bfloat162 h1 = __floats2bfloat162_rn(v.z, v.w);
        __nv_bfloat162 l0 = __floats2bfloat162_rn(v.x - __bfloat162float(h0.x),
                                                  v.y - __bfloat162float(h0.y));
        __nv_bfloat162 l1 = __floats2bfloat162_rn(v.z - __bfloat162float(h1.x),
                                                  v.w - __bfloat162float(h1.y));
        *(__nv_bfloat162*)&outs[(size_t)row * 2 * K + k]         = h0;
        *(__nv_bfloat162*)&outs[(size_t)row * 2 * K + k + 2]     = h1;
        *(__nv_bfloat162*)&outs[(size_t)row * 2 * K + K + k]     = l0;
        *(__nv_bfloat162*)&outs[(size_t)row * 2 * K + K + k + 2] = l1;
    }
    grid_bar();

    // ---- phase 1: T = tanh(y W1^T + b1)  (split precision, 256 tiles) ----
    #pragma unroll 1
    for (int t = cta; t < 256; t += NB) {
        const int nx = t & 15, ny = t >> 4;
        gemm_tile<MODE_TANH, 3>(sb, g_ys, 2 * DIM, g_W1s, 2 * DIM, DIM,
                                g_T, g_Ts, HID, b1, nullptr,
                                ny * 32, nx * 64, 0);
    }
    grid_bar();

    // ---- phase 2: S1 partials = T W2^T  (split, z in 0..3) ----
    #pragma unroll 1
    for (int t = cta; t < 256; t += NB) {
        const int nx = t & 3, ny = (t >> 2) & 15, z = t >> 6;
        gemm_tile<MODE_PART, 3>(sb, g_Ts, 2 * HID, g_W2s, 2 * HID, HID,
                                g_part + (size_t)z * BD, nullptr, DIM,
                                nullptr, nullptr,
                                ny * 32, nx * 64, z * 256);
    }
    grid_bar();

    // ---- phase 3: v = sum(partials) + b2 ; Vp = bf16(v) ----
    {
        const int e4 = (cta * 256 + tid) * 4;
        float4 s0 = *(const float4*)&g_part[e4];
        float4 s1 = *(const float4*)&g_part[BD     + e4];
        float4 s2 = *(const float4*)&g_part[BD * 2 + e4];
        float4 s3 = *(const float4*)&g_part[BD * 3 + e4];
        float4 b  = *(const float4*)&b2[e4 & (DIM - 1)];
        float4 r;
        r.x = (s0.x + s1.x) + (s2.x + s3.x) + b.x;
        r.y = (s0.y + s1.y) + (s2.y + s3.y) + b.y;
        r.z = (s0.z + s1.z) + (s2.z + s3.z) + b.z;
        r.w = (s0.w + s1.w) + (s2.w + s3.w) + b.w;
        *(float4*)&g_V[e4] = r;
        __nv_bfloat162 h0 = __floats2bfloat162_rn(r.x, r.y);
        __nv_bfloat162 h1 = __floats2bfloat162_rn(r.z, r.w);
        *(__nv_bfloat162*)&g_Vp[e4]     = h0;
        *(__nv_bfloat162*)&g_Vp[e4 + 2] = h1;
    }
    grid_bar();

    // ---- phase 4: Pp = (Vp W1^T) .* (1 - T^2)  (plain bf16) ----
    #pragma unroll 1
    for (int t = cta; t < 256; t += NB) {
        const int nx = t & 15, ny = t >> 4;
        gemm_tile<MODE_MULS, 1>(sb, g_Vp, DIM, g_W1s, 2 * DIM, 0,
                                nullptr, g_Pp, HID, nullptr, g_T,
                                ny * 32, nx * 64, 0);
    }
    grid_bar();

    // ---- phase 5: S2 partials = Pp W2^T  (plain, z in 0..3) ----
    #pragma unroll 1
    for (int t = cta; t < 256; t += NB) {
        const int nx = t & 3, ny = (t >> 2) & 15, z = t >> 6;
        gemm_tile<MODE_PART, 1>(sb, g_Pp, HID, g_W2s, 2 * HID, 0,
                                g_part + (size_t)z * BD, nullptr, DIM,
                                nullptr, nullptr,
                                ny * 32, nx * 64, z * 256);
    }
    grid_bar();

    // ---- phase 6: out = v + 1.5*c3 * sum(partials) ----
    {
        const float sc = 1.5f * c3;
        const int e4 = (cta * 256 + tid) * 4;
        float4 s0 = *(const float4*)&g_part[e4];
        float4 s1 = *(const float4*)&g_part[BD     + e4];
        float4 s2 = *(const float4*)&g_part[BD * 2 + e4];
        float4 s3 = *(const float4*)&g_part[BD * 3 + e4];
        float4 b  = *(const float4*)&g_V[e4];
        float4 r;
        r.x = fmaf(sc, (s0.x + s1.x) + (s2.x + s3.x), b.x);
        r.y = fmaf(sc, (s0.y + s1.y) + (s2.y + s3.y), b.y);
        r.z = fmaf(sc, (s0.z + s1.z) + (s2.z + s3.z), b.z);
        r.w = fmaf(sc, (s0.w + s1.w) + (s2.w + s3.w), b.w);
        *(float4*)&out[e4] = r;
    }
}

extern "C" void kernel_launch(void* const* d_in, const int* in_sizes, int n_in,
                              void* d_out, int out_size)
{
    const float* y  = (const float*)d_in[0];
    const float* W1 = (const float*)d_in[1];
    const float* b1 = (const float*)d_in[2];
    const float* W2 = (const float*)d_in[3];
    const float* b2 = (const float*)d_in[4];
    float* out = (float*)d_out;

    fused_all<<<NB, 256>>>(y, W1, b1, W2, b2, out);
}

// round 12
// speedup vs baseline: 1.1769x; 1.1769x over previous
#include <cuda_runtime.h>
#include <cuda_bf16.h>
#include <cstdint>
#include <math.h>

// EulerRosenbrockModel: B=512, D=256, HID=1024, H_STEP=0.01
// out = v + 1.5 B v,  B = (h/3) J   (dropped 1.5 B^2 v ~ 8e-6 rel)
// R10 structure (7 launches) + Programmatic Dependent Launch on every edge:
// each kernel launches its dependent at entry; dependent waits (griddepcontrol)
// before reading predecessor outputs. Overlaps launch ramps with execution.

static constexpr int BATCH = 512;
static constexpr int DIM   = 256;
static constexpr int HID   = 1024;
static constexpr int BD    = BATCH * DIM;

__device__ float g_T   [BATCH * HID];
__device__ float g_V   [BD];
__device__ float g_part[4 * BD];
__device__ __nv_bfloat16 g_ys [BATCH * 2 * DIM];
__device__ __nv_bfloat16 g_W1s[HID   * 2 * DIM];
__device__ __nv_bfloat16 g_W2s[DIM   * 2 * HID];
__device__ __nv_bfloat16 g_Ts [BATCH * 2 * HID];
__device__ __nv_bfloat16 g_Pp [BATCH * HID];
__device__ __nv_bfloat16 g_Vp [BD];

// ---------------- PDL ----------------
#define PDL_LAUNCH_DEPS() asm volatile("griddepcontrol.launch_dependents;")
#define PDL_WAIT()        asm volatile("griddepcontrol.wait;" ::: "memory")

// ---------------- low-level helpers ----------------
__device__ __forceinline__ uint32_t smem_u32(const void* p) {
    uint32_t a;
    asm("{ .reg .u64 t; cvta.to.shared.u64 t, %1; cvt.u32.u64 %0, t; }"
        : "=r"(a) : "l"(p));
    return a;
}
__device__ __forceinline__ void cp16(uint32_t dst, const void* src) {
    asm volatile("cp.async.cg.shared.global [%0], [%1], 16;" :: "r"(dst), "l"(src));
}
__device__ __forceinline__ void cp_commit() {
    asm volatile("cp.async.commit_group;" ::: "memory");
}
template<int N>
__device__ __forceinline__ void cp_wait() {
    asm volatile("cp.async.wait_group %0;" :: "n"(N) : "memory");
}
__device__ __forceinline__ void ldm4(uint32_t* r, uint32_t addr) {
    asm volatile("ldmatrix.sync.aligned.m8n8.x4.shared.b16 {%0,%1,%2,%3}, [%4];"
        : "=r"(r[0]), "=r"(r[1]), "=r"(r[2]), "=r"(r[3]) : "r"(addr));
}
__device__ __forceinline__ void mma_bf16(float* d, const uint32_t* a, const uint32_t* b) {
    asm volatile("mma.sync.aligned.m16n8k16.row.col.f32.bf16.bf16.f32 "
        "{%0,%1,%2,%3}, {%4,%5,%6,%7}, {%8,%9}, {%0,%1,%2,%3};"
        : "+f"(d[0]), "+f"(d[1]), "+f"(d[2]), "+f"(d[3])
        : "r"(a[0]), "r"(a[1]), "r"(a[2]), "r"(a[3]), "r"(b[0]), "r"(b[1]));
}
__device__ __forceinline__ void st_split(__nv_bfloat16* Cs, int Kw, int m, int n,
                                         float v0, float v1) {
    __nv_bfloat162 h = __floats2bfloat162_rn(v0, v1);
    float l0 = v0 - __bfloat162float(h.x);
    float l1 = v1 - __bfloat162float(h.y);
    __nv_bfloat162 l = __floats2bfloat162_rn(l0, l1);
    *(__nv_bfloat162*)&Cs[(size_t)m * (2 * Kw) + n]      = h;
    *(__nv_bfloat162*)&Cs[(size_t)m * (2 * Kw) + Kw + n] = l;
}

#define MODE_TANH 0
#define MODE_MULS 1
#define MODE_PART 2

// CTA tile 32x64, 8 warps, 4-stage cp.async ring, one sync per chunk.
// NREG=3: split precision (12 chunks); NREG=1: plain bf16 (4 chunks).
template<int MODE, int NREG>
__global__ void __launch_bounds__(256)
mmagemm(const __nv_bfloat16* __restrict__ A, int lda,
        const __nv_bfloat16* __restrict__ Bw, int ldb, int Ka,
        float* __restrict__ C, __nv_bfloat16* __restrict__ Cs,
        int Nglob, const float* __restrict__ bias, const float* __restrict__ tanhT)
{
    constexpr int CHUNKS = 4 * NREG;
    constexpr int STAGE  = 12288;           // 4KB A + 8KB B
    __shared__ __align__(1024) char smem[4 * STAGE];
    const uint32_t sb = smem_u32(smem);

    PDL_LAUNCH_DEPS();                       // let successor start its prologue

    const int tid = threadIdx.x;
    const int wid = tid >> 5;
    const int lid = tid & 31;
    const int wm  = wid >> 2;
    const int wn  = wid & 3;
    const int m0  = blockIdx.y * 32;
    const int n0  = blockIdx.x * 64;
    const int zoff = blockIdx.z * 256;

    float acc[2][4];
    #pragma unroll
    for (int g = 0; g < 2; g++)
        #pragma unroll
        for (int q = 0; q < 4; q++) acc[g][q] = 0.0f;

    const int m_l = wm * 16 + ((lid >> 3) & 1) * 8 + (lid & 7);
    const int n_l = wn * 16 + (lid >> 4) * 8 + (lid & 7);
    const int a_so = (lid >> 4);
    const int b_so = ((lid >> 3) & 1);
    const uint32_t ax = (uint32_t)((m_l & 7) << 4);
    const uint32_t bx = (uint32_t)((n_l & 7) << 4);

    auto issue = [&](int cc, int st) {
        const int r  = (NREG == 3) ? (cc >> 2) : 0;
        const int kb = (cc & 3) * 64;
        const int ak = zoff + kb + (r == 2 ? Ka : 0);
        const int bk = zoff + kb + (r == 1 ? Ka : 0);
        const uint32_t ab = sb + st * STAGE;
        const uint32_t bb = ab + 4096;
        #pragma unroll
        for (int t = tid; t < 768; t += 256) {
            const int row = (t & 255) >> 3, seg = t & 7;
            const uint32_t sw = (uint32_t)(seg * 16) ^ (uint32_t)((row & 7) << 4);
            if (t < 256) {
                cp16(ab + row * 128 + sw,
                     A + (size_t)(m0 + row) * lda + ak + seg * 8);
            } else {
                const int rr = t >= 512 ? row + 32 : row;
                cp16(bb + rr * 128 + sw,
                     Bw + (size_t)(n0 + rr) * ldb + bk + seg * 8);
            }
        }
    };

    PDL_WAIT();                              // predecessor outputs now visible

    issue(0, 0); cp_commit();
    issue(1, 1); cp_commit();
    if (CHUNKS > 2) { issue(2, 2); cp_commit(); }

    #pragma unroll 1
    for (int c = 0; c < CHUNKS; c++) {
        const int rem = CHUNKS - 1 - c;
        if (rem >= 2)      cp_wait<2>();
        else if (rem == 1) cp_wait<1>();
        else               cp_wait<0>();
        __syncthreads();
        if (c + 3 < CHUNKS) { issue(c + 3, (c + 3) & 3); cp_commit(); }

        const uint32_t ab = sb + (c & 3) * STAGE;
        const uint32_t aRow = ab + m_l * 128;
        const uint32_t bRow = ab + 4096 + n_l * 128;
        #pragma unroll
        for (int k = 0; k < 4; k++) {
            uint32_t a0[4], b[4];
            const uint32_t as = (uint32_t)((k * 2 + a_so) * 16) ^ ax;
            const uint32_t bs = (uint32_t)((k * 2 + b_so) * 16) ^ bx;
            ldm4(a0, aRow + as);
            ldm4(b,  bRow + bs);
            mma_bf16(acc[0], a0, b);
            mma_bf16(acc[1], a0, b + 2);
        }
    }

    const int gid  = lid >> 2;
    const int tid4 = lid & 3;
    #pragma unroll
    for (int g = 0; g < 2; g++) {
        const int m = m0 + wm * 16 + gid;
        const int n = n0 + wn * 16 + g * 8 + tid4 * 2;
        const float* ac = acc[g];
        if (MODE == MODE_TANH) {
            const float b0v = bias[n], b1v = bias[n + 1];
            float v00 = tanhf(ac[0] + b0v), v01 = tanhf(ac[1] + b1v);
            float v10 = tanhf(ac[2] + b0v), v11 = tanhf(ac[3] + b1v);
            *(float2*)&C[(size_t)m * Nglob + n]       = make_float2(v00, v01);
            *(float2*)&C[(size_t)(m + 8) * Nglob + n] = make_float2(v10, v11);
            st_split(Cs, Nglob, m,     n, v00, v01);
            st_split(Cs, Nglob, m + 8, n, v10, v11);
        } else if (MODE == MODE_MULS) {
            float2 t0 = *(const float2*)&tanhT[(size_t)m * Nglob + n];
            float2 t1 = *(const float2*)&tanhT[(size_t)(m + 8) * Nglob + n];
            __nv_bfloat162 h0 = __floats2bfloat162_rn(
                ac[0] * (1.0f - t0.x * t0.x), ac[1] * (1.0f - t0.y * t0.y));
            __nv_bfloat162 h1 = __floats2bfloat162_rn(
                ac[2] * (1.0f - t1.x * t1.x), ac[3] * (1.0f - t1.y * t1.y));
            *(__nv_bfloat162*)&Cs[(size_t)m * Nglob + n]       = h0;
            *(__nv_bfloat162*)&Cs[(size_t)(m + 8) * Nglob + n] = h1;
        } else {
            float* Cb = C + (size_t)blockIdx.z * BD;
            *(float2*)&Cb[(size_t)m * Nglob + n]       = make_float2(ac[0], ac[1]);
            *(float2*)&Cb[(size_t)(m + 8) * Nglob + n] = make_float2(ac[2], ac[3]);
        }
    }
}

// fused split of y, W1, W2 -> split bf16 panels (one launch)
__global__ void __launch_bounds__(256)
split_all(const float* __restrict__ y, const float* __restrict__ W1,
          const float* __restrict__ W2,
          __nv_bfloat16* __restrict__ ys, __nv_bfloat16* __restrict__ W1s,
          __nv_bfloat16* __restrict__ W2s)
{
    PDL_LAUNCH_DEPS();
    int b = blockIdx.x;
    const float* in;
    __nv_bfloat16* outs;
    int K;
    if (b < 128)      { in = y;  outs = ys;  K = DIM; }
    else if (b < 384) { in = W1; outs = W1s; K = DIM;  b -= 128; }
    else              { in = W2; outs = W2s; K = HID;  b -= 384; }

    const int e4 = (b * 256 + threadIdx.x) * 4;
    const int row = e4 / K, k = e4 % K;
    float4 v = *(const float4*)&in[e4];
    __nv_bfloat162 h0 = __floats2bfloat162_rn(v.x, v.y);
    __nv_bfloat162 h1 = __floats2bfloat162_rn(v.z, v.w);
    __nv_bfloat162 l0 = __floats2bfloat162_rn(v.x - __bfloat162float(h0.x),
                                              v.y - __bfloat162float(h0.y));
    __nv_bfloat162 l1 = __floats2bfloat162_rn(v.z - __bfloat162float(h1.x),
                                              v.w - __bfloat162float(h1.y));
    *(__nv_bfloat162*)&outs[(size_t)row * 2 * K + k]         = h0;
    *(__nv_bfloat162*)&outs[(size_t)row * 2 * K + k + 2]     = h1;
    *(__nv_bfloat162*)&outs[(size_t)row * 2 * K + K + k]     = l0;
    *(__nv_bfloat162*)&outs[(size_t)row * 2 * K + K + k + 2] = l1;
}

// RMODE 0: fp32 out = sum + bias, plain bf16 outs
// RMODE 2: fp32 out = aux + scale*sum
template<int RMODE>
__global__ void __launch_bounds__(256)
reduce_ep(const float* __restrict__ part, const float* __restrict__ aux,
          float scale, float* __restrict__ out, __nv_bfloat16* __restrict__ outs)
{
    PDL_LAUNCH_DEPS();
    const int e4 = (blockIdx.x * 256 + threadIdx.x) * 4;
    PDL_WAIT();
    float4 s0 = *(const float4*)&part[e4];
    float4 s1 = *(const float4*)&part[BD     + e4];
    float4 s2 = *(const float4*)&part[BD * 2 + e4];
    float4 s3 = *(const float4*)&part[BD * 3 + e4];
    float4 r;
    r.x = (s0.x + s1.x) + (s2.x + s3.x);
    r.y = (s0.y + s1.y) + (s2.y + s3.y);
    r.z = (s0.z + s1.z) + (s2.z + s3.z);
    r.w = (s0.w + s1.w) + (s2.w + s3.w);
    if (RMODE == 0) {
        float4 b = *(const float4*)&aux[e4 & (DIM - 1)];
        r.x += b.x; r.y += b.y; r.z += b.z; r.w += b.w;
        *(float4*)&out[e4] = r;
        __nv_bfloat162 h0 = __floats2bfloat162_rn(r.x, r.y);
        __nv_bfloat162 h1 = __floats2bfloat162_rn(r.z, r.w);
        *(__nv_bfloat162*)&outs[e4]     = h0;
        *(__nv_bfloat162*)&outs[e4 + 2] = h1;
    } else {
        float4 b = *(const float4*)&aux[e4];
        r.x = fmaf(scale, r.x, b.x); r.y = fmaf(scale, r.y, b.y);
        r.z = fmaf(scale, r.z, b.z); r.w = fmaf(scale, r.w, b.w);
        *(float4*)&out[e4] = r;
    }
}

// ---- host: PDL launch helper ----
template<typename F, typename... Args>
static inline void launch_pdl(F* kern, dim3 grid, dim3 block, Args... args) {
    cudaLaunchConfig_t cfg = {};
    cfg.gridDim = grid;
    cfg.blockDim = block;
    cfg.dynamicSmemBytes = 0;
    cfg.stream = 0;
    cudaLaunchAttribute attr[1];
    attr[0].id = cudaLaunchAttributeProgrammaticStreamSerialization;
    attr[0].val.programmaticStreamSerializationAllowed = 1;
    cfg.attrs = attr;
    cfg.numAttrs = 1;
    cudaLaunchKernelEx(&cfg, kern, args...);
}

extern "C" void kernel_launch(void* const* d_in, const int* in_sizes, int n_in,
                              void* d_out, int out_size)
{
    const float* y  = (const float*)d_in[0];
    const float* W1 = (const float*)d_in[1];
    const float* b1 = (const float*)d_in[2];
    const float* W2 = (const float*)d_in[3];
    const float* b2 = (const float*)d_in[4];
    float* out = (float*)d_out;

    float *pT, *pV, *pPart;
    __nv_bfloat16 *pYs, *pW1s, *pW2s, *pTs, *pPp, *pVp;
    cudaGetSymbolAddress((void**)&pT,    g_T);
    cudaGetSymbolAddress((void**)&pV,    g_V);
    cudaGetSymbolAddress((void**)&pPart, g_part);
    cudaGetSymbolAddress((void**)&pYs,   g_ys);
    cudaGetSymbolAddress((void**)&pW1s,  g_W1s);
    cudaGetSymbolAddress((void**)&pW2s,  g_W2s);
    cudaGetSymbolAddress((void**)&pTs,   g_Ts);
    cudaGetSymbolAddress((void**)&pPp,   g_Pp);
    cudaGetSymbolAddress((void**)&pVp,   g_Vp);

    dim3 gL(HID / 64, BATCH / 32, 1);   // (16,16,1) = 256 CTAs
    dim3 gS(DIM / 64, BATCH / 32, 4);   // ( 4,16,4) = 256 CTAs
    dim3 gR(BD / (256 * 4), 1, 1);      // 128
    dim3 blk(256, 1, 1);

    const float c3 = 0.01f / 3.0f;

    split_all<<<640, 256>>>(y, W1, W2, pYs, pW1s, pW2s);

    // forward (split precision): T = tanh(y W1^T + b1);  V = T W2^T + b2
    launch_pdl(&mmagemm<MODE_TANH, 3>, gL, blk,
               (const __nv_bfloat16*)pYs, 2 * DIM,
               (const __nv_bfloat16*)pW1s, 2 * DIM, DIM,
               pT, pTs, HID, b1, (const float*)nullptr);
    launch_pdl(&mmagemm<MODE_PART, 3>, gS, blk,
               (const __nv_bfloat16*)pTs, 2 * HID,
               (const __nv_bfloat16*)pW2s, 2 * HID, HID,
               pPart, (__nv_bfloat16*)nullptr, DIM,
               (const float*)nullptr, (const float*)nullptr);
    launch_pdl(&reduce_ep<0>, gR, blk,
               (const float*)pPart, b2, 0.0f, pV, pVp);

    // out = v + 1.5 B v   (single correction, plain bf16)
    launch_pdl(&mmagemm<MODE_MULS, 1>, gL, blk,
               (const __nv_bfloat16*)pVp, DIM,
               (const __nv_bfloat16*)pW1s, 2 * DIM, 0,
               (float*)nullptr, pPp, HID,
               (const float*)nullptr, (const float*)pT);
    launch_pdl(&mmagemm<MODE_PART, 1>, gS, blk,
               (const __nv_bfloat16*)pPp, HID,
               (const __nv_bfloat16*)pW2s, 2 * HID, 0,
               pPart, (__nv_bfloat16*)nullptr, DIM,
               (const float*)nullptr, (const float*)nullptr);
    launch_pdl(&reduce_ep<2>, gR, blk,
               (const float*)pPart, (const float*)pV, 1.5f * c3,
               out, (__nv_bfloat16*)nullptr);
}

// round 13
// speedup vs baseline: 1.2446x; 1.0576x over previous
#include <cuda_runtime.h>
#include <cuda_bf16.h>
#include <cstdint>
#include <math.h>

// EulerRosenbrockModel: B=512, D=256, HID=1024, H_STEP=0.01
// out = v + 1.5 B v,  B = (h/3) J   (dropped 1.5 B^2 v ~ 8e-6 rel)
// 5 launches: split | L1 (tanh, split bf16) | S1 (full-K, bias epilogue) |
//             L2 (muls, plain bf16) | S2 (full-K, AXPY epilogue -> out).
// S GEMMs: 32x32 tiles, 128 CTAs, full K in-register (no split-K, no reduce).

static constexpr int BATCH = 512;
static constexpr int DIM   = 256;
static constexpr int HID   = 1024;
static constexpr int BD    = BATCH * DIM;

__device__ float g_T [BATCH * HID];
__device__ float g_V [BD];
__device__ __nv_bfloat16 g_ys [BATCH * 2 * DIM];
__device__ __nv_bfloat16 g_W1s[HID   * 2 * DIM];
__device__ __nv_bfloat16 g_W2s[DIM   * 2 * HID];
__device__ __nv_bfloat16 g_Ts [BATCH * 2 * HID];
__device__ __nv_bfloat16 g_Pp [BATCH * HID];
__device__ __nv_bfloat16 g_Vp [BD];

// ---------------- low-level helpers ----------------
__device__ __forceinline__ uint32_t smem_u32(const void* p) {
    uint32_t a;
    asm("{ .reg .u64 t; cvta.to.shared.u64 t, %1; cvt.u32.u64 %0, t; }"
        : "=r"(a) : "l"(p));
    return a;
}
__device__ __forceinline__ void cp16(uint32_t dst, const void* src) {
    asm volatile("cp.async.cg.shared.global [%0], [%1], 16;" :: "r"(dst), "l"(src));
}
__device__ __forceinline__ void cp_commit() {
    asm volatile("cp.async.commit_group;" ::: "memory");
}
template<int N>
__device__ __forceinline__ void cp_wait() {
    asm volatile("cp.async.wait_group %0;" :: "n"(N) : "memory");
}
__device__ __forceinline__ void ldm4(uint32_t* r, uint32_t addr) {
    asm volatile("ldmatrix.sync.aligned.m8n8.x4.shared.b16 {%0,%1,%2,%3}, [%4];"
        : "=r"(r[0]), "=r"(r[1]), "=r"(r[2]), "=r"(r[3]) : "r"(addr));
}
__device__ __forceinline__ void ldm2(uint32_t* r, uint32_t addr) {
    asm volatile("ldmatrix.sync.aligned.m8n8.x2.shared.b16 {%0,%1}, [%2];"
        : "=r"(r[0]), "=r"(r[1]) : "r"(addr));
}
__device__ __forceinline__ void mma_bf16(float* d, const uint32_t* a, const uint32_t* b) {
    asm volatile("mma.sync.aligned.m16n8k16.row.col.f32.bf16.bf16.f32 "
        "{%0,%1,%2,%3}, {%4,%5,%6,%7}, {%8,%9}, {%0,%1,%2,%3};"
        : "+f"(d[0]), "+f"(d[1]), "+f"(d[2]), "+f"(d[3])
        : "r"(a[0]), "r"(a[1]), "r"(a[2]), "r"(a[3]), "r"(b[0]), "r"(b[1]));
}
__device__ __forceinline__ void st_split(__nv_bfloat16* Cs, int Kw, int m, int n,
                                         float v0, float v1) {
    __nv_bfloat162 h = __floats2bfloat162_rn(v0, v1);
    float l0 = v0 - __bfloat162float(h.x);
    float l1 = v1 - __bfloat162float(h.y);
    __nv_bfloat162 l = __floats2bfloat162_rn(l0, l1);
    *(__nv_bfloat162*)&Cs[(size_t)m * (2 * Kw) + n]      = h;
    *(__nv_bfloat162*)&Cs[(size_t)m * (2 * Kw) + Kw + n] = l;
}

#define MODE_TANH 0
#define MODE_MULS 1

// -------- L-shape GEMM (512 x 1024, K = 256 f32): CTA tile 32x64 ----------
// 8 warps = 2(m) x 4(n), warp tile 16x16. 4-stage cp.async ring.
// NREG=3: split precision (12 chunks); NREG=1: plain bf16 (4 chunks).
template<int MODE, int NREG>
__global__ void __launch_bounds__(256)
mmagemm(const __nv_bfloat16* __restrict__ A, int lda,
        const __nv_bfloat16* __restrict__ Bw, int ldb, int Ka,
        float* __restrict__ C, __nv_bfloat16* __restrict__ Cs,
        int Nglob, const float* __restrict__ bias, const float* __restrict__ tanhT)
{
    constexpr int CHUNKS = 4 * NREG;
    constexpr int STAGE  = 12288;           // 4KB A + 8KB B
    __shared__ __align__(1024) char smem[4 * STAGE];
    const uint32_t sb = smem_u32(smem);

    const int tid = threadIdx.x;
    const int wid = tid >> 5;
    const int lid = tid & 31;
    const int wm  = wid >> 2;
    const int wn  = wid & 3;
    const int m0  = blockIdx.y * 32;
    const int n0  = blockIdx.x * 64;

    float acc[2][4];
    #pragma unroll
    for (int g = 0; g < 2; g++)
        #pragma unroll
        for (int q = 0; q < 4; q++) acc[g][q] = 0.0f;

    const int m_l = wm * 16 + ((lid >> 3) & 1) * 8 + (lid & 7);
    const int n_l = wn * 16 + (lid >> 4) * 8 + (lid & 7);
    const int a_so = (lid >> 4);
    const int b_so = ((lid >> 3) & 1);
    const uint32_t ax = (uint32_t)((m_l & 7) << 4);
    const uint32_t bx = (uint32_t)((n_l & 7) << 4);

    auto issue = [&](int cc, int st) {
        const int r  = (NREG == 3) ? (cc >> 2) : 0;
        const int kb = (cc & 3) * 64;
        const int ak = kb + (r == 2 ? Ka : 0);
        const int bk = kb + (r == 1 ? Ka : 0);
        const uint32_t ab = sb + st * STAGE;
        const uint32_t bb = ab + 4096;
        #pragma unroll
        for (int t = tid; t < 768; t += 256) {
            const int row = (t & 255) >> 3, seg = t & 7;
            const uint32_t sw = (uint32_t)(seg * 16) ^ (uint32_t)((row & 7) << 4);
            if (t < 256) {
                cp16(ab + row * 128 + sw,
                     A + (size_t)(m0 + row) * lda + ak + seg * 8);
            } else {
                const int rr = t >= 512 ? row + 32 : row;
                cp16(bb + rr * 128 + sw,
                     Bw + (size_t)(n0 + rr) * ldb + bk + seg * 8);
            }
        }
    };

    issue(0, 0); cp_commit();
    issue(1, 1); cp_commit();
    if (CHUNKS > 2) { issue(2, 2); cp_commit(); }

    #pragma unroll 1
    for (int c = 0; c < CHUNKS; c++) {
        const int rem = CHUNKS - 1 - c;
        if (rem >= 2)      cp_wait<2>();
        else if (rem == 1) cp_wait<1>();
        else               cp_wait<0>();
        __syncthreads();
        if (c + 3 < CHUNKS) { issue(c + 3, (c + 3) & 3); cp_commit(); }

        const uint32_t ab = sb + (c & 3) * STAGE;
        const uint32_t aRow = ab + m_l * 128;
        const uint32_t bRow = ab + 4096 + n_l * 128;
        #pragma unroll
        for (int k = 0; k < 4; k++) {
            uint32_t a0[4], b[4];
            const uint32_t as = (uint32_t)((k * 2 + a_so) * 16) ^ ax;
            const uint32_t bs = (uint32_t)((k * 2 + b_so) * 16) ^ bx;
            ldm4(a0, aRow + as);
            ldm4(b,  bRow + bs);
            mma_bf16(acc[0], a0, b);
            mma_bf16(acc[1], a0, b + 2);
        }
    }

    const int gid  = lid >> 2;
    const int tid4 = lid & 3;
    #pragma unroll
    for (int g = 0; g < 2; g++) {
        const int m = m0 + wm * 16 + gid;
        const int n = n0 + wn * 16 + g * 8 + tid4 * 2;
        const float* ac = acc[g];
        if (MODE == MODE_TANH) {
            const float b0v = bias[n], b1v = bias[n + 1];
            float v00 = tanhf(ac[0] + b0v), v01 = tanhf(ac[1] + b1v);
            float v10 = tanhf(ac[2] + b0v), v11 = tanhf(ac[3] + b1v);
            *(float2*)&C[(size_t)m * Nglob + n]       = make_float2(v00, v01);
            *(float2*)&C[(size_t)(m + 8) * Nglob + n] = make_float2(v10, v11);
            st_split(Cs, Nglob, m,     n, v00, v01);
            st_split(Cs, Nglob, m + 8, n, v10, v11);
        } else {
            float2 t0 = *(const float2*)&tanhT[(size_t)m * Nglob + n];
            float2 t1 = *(const float2*)&tanhT[(size_t)(m + 8) * Nglob + n];
            __nv_bfloat162 h0 = __floats2bfloat162_rn(
                ac[0] * (1.0f - t0.x * t0.x), ac[1] * (1.0f - t0.y * t0.y));
            __nv_bfloat162 h1 = __floats2bfloat162_rn(
                ac[2] * (1.0f - t1.x * t1.x), ac[3] * (1.0f - t1.y * t1.y));
            *(__nv_bfloat162*)&Cs[(size_t)m * Nglob + n]       = h0;
            *(__nv_bfloat162*)&Cs[(size_t)(m + 8) * Nglob + n] = h1;
        }
    }
}

// -------- S-shape GEMM (512 x 256, K = 1024 f32 FULL): CTA tile 32x32 ------
// grid (8,16) = 128 CTAs. 8 warps = 2(m) x 4(n), warp tile 16x8 (ldmatrix.x2
// for B). Full K in-register (no split-K). Direct epilogue.
// RMODE 0: v = acc + bias[n] -> g_V fp32 + g_Vp bf16
// RMODE 1: out = aux + scale*acc (fp32)
template<int NREG, int RMODE>
__global__ void __launch_bounds__(256)
sgemm_full(const __nv_bfloat16* __restrict__ A, int lda,
           const __nv_bfloat16* __restrict__ Bw, int ldb, int Ka,
           const float* __restrict__ aux, float scale,
           float* __restrict__ outF, __nv_bfloat16* __restrict__ outB)
{
    constexpr int CHUNKS = 16 * NREG;       // 16 k-chunks of 64 per region
    constexpr int STAGE  = 8192;            // 4KB A + 4KB B
    __shared__ __align__(1024) char smem[4 * STAGE];
    const uint32_t sb = smem_u32(smem);

    const int tid = threadIdx.x;
    const int wid = tid >> 5;
    const int lid = tid & 31;
    const int wm  = wid >> 2;               // 0..1
    const int wn  = wid & 3;                // 0..3
    const int m0  = blockIdx.y * 32;
    const int n0  = blockIdx.x * 32;

    float acc[4];
    #pragma unroll
    for (int q = 0; q < 4; q++) acc[q] = 0.0f;

    const int m_l  = wm * 16 + ((lid >> 3) & 1) * 8 + (lid & 7);
    const int a_so = (lid >> 4);
    const int n_l2 = wn * 8 + (lid & 7);
    const int b_sg = (lid >> 3) & 1;        // 0: k0-7, 1: k8-15
    const uint32_t ax = (uint32_t)((m_l & 7) << 4);
    const uint32_t bx = (uint32_t)((n_l2 & 7) << 4);

    auto issue = [&](int cc, int st) {
        const int r  = (NREG == 3) ? (cc >> 4) : 0;
        const int kb = (cc & 15) * 64;
        const int ak = kb + (r == 2 ? Ka : 0);
        const int bk = kb + (r == 1 ? Ka : 0);
        const uint32_t ab = sb + st * STAGE;
        const uint32_t bb = ab + 4096;
        #pragma unroll
        for (int t = tid; t < 512; t += 256) {
            const int row = (t & 255) >> 3, seg = t & 7;
            const uint32_t sw = (uint32_t)(seg * 16) ^ (uint32_t)((row & 7) << 4);
            if (t < 256)
                cp16(ab + row * 128 + sw,
                     A + (size_t)(m0 + row) * lda + ak + seg * 8);
            else
                cp16(bb + row * 128 + sw,
                     Bw + (size_t)(n0 + row) * ldb + bk + seg * 8);
        }
    };

    issue(0, 0); cp_commit();
    issue(1, 1); cp_commit();
    issue(2, 2); cp_commit();

    #pragma unroll 1
    for (int c = 0; c < CHUNKS; c++) {
        const int rem = CHUNKS - 1 - c;
        if (rem >= 2)      cp_wait<2>();
        else if (rem == 1) cp_wait<1>();
        else               cp_wait<0>();
        __syncthreads();
        if (c + 3 < CHUNKS) { issue(c + 3, (c + 3) & 3); cp_commit(); }

        const uint32_t ab = sb + (c & 3) * STAGE;
        const uint32_t aRow = ab + m_l * 128;
        const uint32_t bRow = ab + 4096 + n_l2 * 128;
        #pragma unroll
        for (int k = 0; k < 4; k++) {
            uint32_t a0[4], b[2];
            const uint32_t as = (uint32_t)((k * 2 + a_so) * 16) ^ ax;
            const uint32_t bs = (uint32_t)((k * 2 + b_sg) * 16) ^ bx;
            ldm4(a0, aRow + as);
            ldm2(b,  bRow + bs);
            mma_bf16(acc, a0, b);
        }
    }

    const int gid  = lid >> 2;
    const int tid4 = lid & 3;
    const int m = m0 + wm * 16 + gid;
    const int n = n0 + wn * 8 + tid4 * 2;
    if (RMODE == 0) {
        const float b0v = aux[n], b1v = aux[n + 1];   // aux = b2 (per-col bias)
        float v00 = acc[0] + b0v, v01 = acc[1] + b1v;
        float v10 = acc[2] + b0v, v11 = acc[3] + b1v;
        *(float2*)&outF[(size_t)m * DIM + n]       = make_float2(v00, v01);
        *(float2*)&outF[(size_t)(m + 8) * DIM + n] = make_float2(v10, v11);
        *(__nv_bfloat162*)&outB[(size_t)m * DIM + n] =
            __floats2bfloat162_rn(v00, v01);
        *(__nv_bfloat162*)&outB[(size_t)(m + 8) * DIM + n] =
            __floats2bfloat162_rn(v10, v11);
    } else {
        float2 a0v = *(const float2*)&aux[(size_t)m * DIM + n];
        float2 a1v = *(const float2*)&aux[(size_t)(m + 8) * DIM + n];
        *(float2*)&outF[(size_t)m * DIM + n] =
            make_float2(fmaf(scale, acc[0], a0v.x), fmaf(scale, acc[1], a0v.y));
        *(float2*)&outF[(size_t)(m + 8) * DIM + n] =
            make_float2(fmaf(scale, acc[2], a1v.x), fmaf(scale, acc[3], a1v.y));
    }
}

// fused split of y, W1, W2 -> split bf16 panels (one launch)
__global__ void __launch_bounds__(256)
split_all(const float* __restrict__ y, const float* __restrict__ W1,
          const float* __restrict__ W2,
          __nv_bfloat16* __restrict__ ys, __nv_bfloat16* __restrict__ W1s,
          __nv_bfloat16* __restrict__ W2s)
{
    int b = blockIdx.x;
    const float* in;
    __nv_bfloat16* outs;
    int K;
    if (b < 128)      { in = y;  outs = ys;  K = DIM; }
    else if (b < 384) { in = W1; outs = W1s; K = DIM;  b -= 128; }
    else              { in = W2; outs = W2s; K = HID;  b -= 384; }

    const int e4 = (b * 256 + threadIdx.x) * 4;
    const int row = e4 / K, k = e4 % K;
    float4 v = *(const float4*)&in[e4];
    __nv_bfloat162 h0 = __floats2bfloat162_rn(v.x, v.y);
    __nv_bfloat162 h1 = __floats2bfloat162_rn(v.z, v.w);
    __nv_bfloat162 l0 = __floats2bfloat162_rn(v.x - __bfloat162float(h0.x),
                                              v.y - __bfloat162float(h0.y));
    __nv_bfloat162 l1 = __floats2bfloat162_rn(v.z - __bfloat162float(h1.x),
                                              v.w - __bfloat162float(h1.y));
    *(__nv_bfloat162*)&outs[(size_t)row * 2 * K + k]         = h0;
    *(__nv_bfloat162*)&outs[(size_t)row * 2 * K + k + 2]     = h1;
    *(__nv_bfloat162*)&outs[(size_t)row * 2 * K + K + k]     = l0;
    *(__nv_bfloat162*)&outs[(size_t)row * 2 * K + K + k + 2] = l1;
}

extern "C" void kernel_launch(void* const* d_in, const int* in_sizes, int n_in,
                              void* d_out, int out_size)
{
    const float* y  = (const float*)d_in[0];
    const float* W1 = (const float*)d_in[1];
    const float* b1 = (const float*)d_in[2];
    const float* W2 = (const float*)d_in[3];
    const float* b2 = (const float*)d_in[4];
    float* out = (float*)d_out;

    float *pT, *pV;
    __nv_bfloat16 *pYs, *pW1s, *pW2s, *pTs, *pPp, *pVp;
    cudaGetSymbolAddress((void**)&pT,   g_T);
    cudaGetSymbolAddress((void**)&pV,   g_V);
    cudaGetSymbolAddress((void**)&pYs,  g_ys);
    cudaGetSymbolAddress((void**)&pW1s, g_W1s);
    cudaGetSymbolAddress((void**)&pW2s, g_W2s);
    cudaGetSymbolAddress((void**)&pTs,  g_Ts);
    cudaGetSymbolAddress((void**)&pPp,  g_Pp);
    cudaGetSymbolAddress((void**)&pVp,  g_Vp);

    dim3 gL(HID / 64, BATCH / 32);   // (16,16) = 256 CTAs
    dim3 gS(DIM / 32, BATCH / 32);   // ( 8,16) = 128 CTAs

    const float c3 = 0.01f / 3.0f;

    split_all<<<640, 256>>>(y, W1, W2, pYs, pW1s, pW2s);

    // T = tanh(y W1^T + b1)            (split precision)
    mmagemm<MODE_TANH, 3><<<gL, 256>>>(pYs, 2 * DIM, pW1s, 2 * DIM, DIM,
                                       pT, pTs, HID, b1, nullptr);
    // v = T W2^T + b2                  (split precision, full K)
    sgemm_full<3, 0><<<gS, 256>>>(pTs, 2 * HID, pW2s, 2 * HID, HID,
                                  b2, 0.0f, pV, pVp);
    // Pp = (Vp W1^T) .* (1 - T^2)      (plain bf16)
    mmagemm<MODE_MULS, 1><<<gL, 256>>>(pVp, DIM, pW1s, 2 * DIM, 0,
                                       nullptr, pPp, HID, nullptr, pT);
    // out = v + 1.5*c3 * (Pp W2^T)     (plain bf16, full K)
    sgemm_full<1, 1><<<gS, 256>>>(pPp, HID, pW2s, 2 * HID, 0,
                                  pV, 1.5f * c3, out, nullptr);
}

// round 14
// speedup vs baseline: 1.4180x; 1.1393x over previous
#include <cuda_runtime.h>
#include <cuda_fp16.h>
#include <cstdint>
#include <math.h>

// EulerRosenbrockModel: B=512, D=256, HID=1024, H_STEP=0.01
// out = v + 1.5 B v,  B = (h/3) J   (dropped 1.5 B^2 v ~ 8e-6 rel)
// R10 structure (7 launches). fp16 double-split (hi + 2048*lo), 3 regions:
//   hi*hi   -> mma f32-accumulate (exact inputs, accurate v)
//   cross   -> mma f16-accumulate (result ~2^-11 of main; /2048 on combine)
//   corrections -> plain fp16, f16-accumulate (2e-6 on output)
// f16-acc HMMA runs 2x f32-acc on the legacy tensor path.

static constexpr int BATCH = 512;
static constexpr int DIM   = 256;
static constexpr int HID   = 1024;
static constexpr int BD    = BATCH * DIM;
static constexpr float LO_SCALE = 2048.0f;      // keep lo panels in normal fp16

__device__ float g_T   [BATCH * HID];
__device__ float g_V   [BD];
__device__ float g_part[4 * BD];
__device__ __half g_ys [BATCH * 2 * DIM];
__device__ __half g_W1s[HID   * 2 * DIM];
__device__ __half g_W2s[DIM   * 2 * HID];
__device__ __half g_Ts [BATCH * 2 * HID];
__device__ __half g_Pp [BATCH * HID];
__device__ __half g_Vp [BD];

// ---------------- low-level helpers ----------------
__device__ __forceinline__ uint32_t smem_u32(const void* p) {
    uint32_t a;
    asm("{ .reg .u64 t; cvta.to.shared.u64 t, %1; cvt.u32.u64 %0, t; }"
        : "=r"(a) : "l"(p));
    return a;
}
__device__ __forceinline__ void cp16(uint32_t dst, const void* src) {
    asm volatile("cp.async.cg.shared.global [%0], [%1], 16;" :: "r"(dst), "l"(src));
}
__device__ __forceinline__ void cp_commit() {
    asm volatile("cp.async.commit_group;" ::: "memory");
}
template<int N>
__device__ __forceinline__ void cp_wait() {
    asm volatile("cp.async.wait_group %0;" :: "n"(N) : "memory");
}
__device__ __forceinline__ void ldm4(uint32_t* r, uint32_t addr) {
    asm volatile("ldmatrix.sync.aligned.m8n8.x4.shared.b16 {%0,%1,%2,%3}, [%4];"
        : "=r"(r[0]), "=r"(r[1]), "=r"(r[2]), "=r"(r[3]) : "r"(addr));
}
// fp16 inputs, f32 accumulate (main region)
__device__ __forceinline__ void mma_f32(float* d, const uint32_t* a, const uint32_t* b) {
    asm volatile("mma.sync.aligned.m16n8k16.row.col.f32.f16.f16.f32 "
        "{%0,%1,%2,%3}, {%4,%5,%6,%7}, {%8,%9}, {%0,%1,%2,%3};"
        : "+f"(d[0]), "+f"(d[1]), "+f"(d[2]), "+f"(d[3])
        : "r"(a[0]), "r"(a[1]), "r"(a[2]), "r"(a[3]), "r"(b[0]), "r"(b[1]));
}
// fp16 inputs, f16 accumulate (cross regions + corrections, 2x rate)
__device__ __forceinline__ void mma_h(uint32_t* d, const uint32_t* a, const uint32_t* b) {
    asm volatile("mma.sync.aligned.m16n8k16.row.col.f16.f16.f16.f16 "
        "{%0,%1}, {%2,%3,%4,%5}, {%6,%7}, {%0,%1};"
        : "+r"(d[0]), "+r"(d[1])
        : "r"(a[0]), "r"(a[1]), "r"(a[2]), "r"(a[3]), "r"(b[0]), "r"(b[1]));
}
// store fp32 pair as fp16 hi + 2048*lo split at Cs[m][n], layout [m][hi K|lo K]
__device__ __forceinline__ void st_split(__half* Cs, int Kw, int m, int n,
                                         float v0, float v1) {
    __half2 h = __floats2half2_rn(v0, v1);
    float l0 = (v0 - __half2float(h.x)) * LO_SCALE;
    float l1 = (v1 - __half2float(h.y)) * LO_SCALE;
    __half2 l = __floats2half2_rn(l0, l1);
    *(__half2*)&Cs[(size_t)m * (2 * Kw) + n]      = h;
    *(__half2*)&Cs[(size_t)m * (2 * Kw) + Kw + n] = l;
}

#define MODE_TANH 0
#define MODE_MULS 1
#define MODE_PART 2

// CTA tile 32x64, 8 warps, 4-stage cp.async ring, one sync per chunk.
// NREG=3: chunks 0-3 hi*hi (f32 acc), 4-11 cross (f16 acc, /2048 on combine).
// NREG=1: plain fp16, 4 chunks, all f16 acc.
template<int MODE, int NREG>
__global__ void __launch_bounds__(256)
mmagemm(const __half* __restrict__ A, int lda,
        const __half* __restrict__ Bw, int ldb, int Ka,
        float* __restrict__ C, __half* __restrict__ Cs,
        int Nglob, const float* __restrict__ bias, const float* __restrict__ tanhT)
{
    constexpr int CHUNKS = 4 * NREG;
    constexpr int STAGE  = 12288;           // 4KB A + 8KB B
    __shared__ __align__(1024) char smem[4 * STAGE];
    const uint32_t sb = smem_u32(smem);

    const int tid = threadIdx.x;
    const int wid = tid >> 5;
    const int lid = tid & 31;
    const int wm  = wid >> 2;
    const int wn  = wid & 3;
    const int m0  = blockIdx.y * 32;
    const int n0  = blockIdx.x * 64;
    const int zoff = blockIdx.z * 256;

    float acc[2][4];
    uint32_t acch[2][2];
    #pragma unroll
    for (int g = 0; g < 2; g++) {
        #pragma unroll
        for (int q = 0; q < 4; q++) acc[g][q] = 0.0f;
        acch[g][0] = 0u; acch[g][1] = 0u;
    }

    const int m_l = wm * 16 + ((lid >> 3) & 1) * 8 + (lid & 7);
    const int n_l = wn * 16 + (lid >> 4) * 8 + (lid & 7);
    const int a_so = (lid >> 4);
    const int b_so = ((lid >> 3) & 1);
    const uint32_t ax = (uint32_t)((m_l & 7) << 4);
    const uint32_t bx = (uint32_t)((n_l & 7) << 4);

    auto issue = [&](int cc, int st) {
        const int r  = (NREG == 3) ? (cc >> 2) : 0;
        const int kb = (cc & 3) * 64;
        const int ak = zoff + kb + (r == 2 ? Ka : 0);
        const int bk = zoff + kb + (r == 1 ? Ka : 0);
        const uint32_t ab = sb + st * STAGE;
        const uint32_t bb = ab + 4096;
        #pragma unroll
        for (int t = tid; t < 768; t += 256) {
            const int row = (t & 255) >> 3, seg = t & 7;
            const uint32_t sw = (uint32_t)(seg * 16) ^ (uint32_t)((row & 7) << 4);
            if (t < 256) {
                cp16(ab + row * 128 + sw,
                     A + (size_t)(m0 + row) * lda + ak + seg * 8);
            } else {
                const int rr = t >= 512 ? row + 32 : row;
                cp16(bb + rr * 128 + sw,
                     Bw + (size_t)(n0 + rr) * ldb + bk + seg * 8);
            }
        }
    };

    issue(0, 0); cp_commit();
    issue(1, 1); cp_commit();
    if (CHUNKS > 2) { issue(2, 2); cp_commit(); }

    #pragma unroll 1
    for (int c = 0; c < CHUNKS; c++) {
        const int rem = CHUNKS - 1 - c;
        if (rem >= 2)      cp_wait<2>();
        else if (rem == 1) cp_wait<1>();
        else               cp_wait<0>();
        __syncthreads();
        if (c + 3 < CHUNKS) { issue(c + 3, (c + 3) & 3); cp_commit(); }

        const uint32_t ab = sb + (c & 3) * STAGE;
        const uint32_t aRow = ab + m_l * 128;
        const uint32_t bRow = ab + 4096 + n_l * 128;
        if (NREG == 3 && c < 4) {
            #pragma unroll
            for (int k = 0; k < 4; k++) {
                uint32_t a0[4], b[4];
                const uint32_t as = (uint32_t)((k * 2 + a_so) * 16) ^ ax;
                const uint32_t bs = (uint32_t)((k * 2 + b_so) * 16) ^ bx;
                ldm4(a0, aRow + as);
                ldm4(b,  bRow + bs);
                mma_f32(acc[0], a0, b);
                mma_f32(acc[1], a0, b + 2);
            }
        } else {
            #pragma unroll
            for (int k = 0; k < 4; k++) {
                uint32_t a0[4], b[4];
                const uint32_t as = (uint32_t)((k * 2 + a_so) * 16) ^ ax;
                const uint32_t bs = (uint32_t)((k * 2 + b_so) * 16) ^ bx;
                ldm4(a0, aRow + as);
                ldm4(b,  bRow + bs);
                mma_h(acch[0], a0, b);
                mma_h(acch[1], a0, b + 2);
            }
        }
    }

    // combine f16 accumulator into f32 (cross regions carry 2048x lo scale)
    const float cs = (NREG == 3) ? (1.0f / LO_SCALE) : 1.0f;
    #pragma unroll
    for (int g = 0; g < 2; g++) {
        __half2 h0 = *(__half2*)&acch[g][0];
        __half2 h1 = *(__half2*)&acch[g][1];
        acc[g][0] += __half2float(h0.x) * cs;
        acc[g][1] += __half2float(h0.y) * cs;
        acc[g][2] += __half2float(h1.x) * cs;
        acc[g][3] += __half2float(h1.y) * cs;
    }

    const int gid  = lid >> 2;
    const int tid4 = lid & 3;
    #pragma unroll
    for (int g = 0; g < 2; g++) {
        const int m = m0 + wm * 16 + gid;
        const int n = n0 + wn * 16 + g * 8 + tid4 * 2;
        const float* ac = acc[g];
        if (MODE == MODE_TANH) {
            const float b0v = bias[n], b1v = bias[n + 1];
            float v00 = tanhf(ac[0] + b0v), v01 = tanhf(ac[1] + b1v);
            float v10 = tanhf(ac[2] + b0v), v11 = tanhf(ac[3] + b1v);
            *(float2*)&C[(size_t)m * Nglob + n]       = make_float2(v00, v01);
            *(float2*)&C[(size_t)(m + 8) * Nglob + n] = make_float2(v10, v11);
            st_split(Cs, Nglob, m,     n, v00, v01);
            st_split(Cs, Nglob, m + 8, n, v10, v11);
        } else if (MODE == MODE_MULS) {
            float2 t0 = *(const float2*)&tanhT[(size_t)m * Nglob + n];
            float2 t1 = *(const float2*)&tanhT[(size_t)(m + 8) * Nglob + n];
            __half2 h0 = __floats2half2_rn(
                ac[0] * (1.0f - t0.x * t0.x), ac[1] * (1.0f - t0.y * t0.y));
            __half2 h1 = __floats2half2_rn(
                ac[2] * (1.0f - t1.x * t1.x), ac[3] * (1.0f - t1.y * t1.y));
            *(__half2*)&Cs[(size_t)m * Nglob + n]       = h0;
            *(__half2*)&Cs[(size_t)(m + 8) * Nglob + n] = h1;
        } else {
            float* Cb = C + (size_t)blockIdx.z * BD;
            *(float2*)&Cb[(size_t)m * Nglob + n]       = make_float2(ac[0], ac[1]);
            *(float2*)&Cb[(size_t)(m + 8) * Nglob + n] = make_float2(ac[2], ac[3]);
        }
    }
}

// fused split of y, W1, W2 -> fp16 [hi | 2048*lo] panels (one launch)
__global__ void __launch_bounds__(256)
split_all(const float* __restrict__ y, const float* __restrict__ W1,
          const float* __restrict__ W2,
          __half* __restrict__ ys, __half* __restrict__ W1s,
          __half* __restrict__ W2s)
{
    int b = blockIdx.x;
    const float* in;
    __half* outs;
    int K;
    if (b < 128)      { in = y;  outs = ys;  K = DIM; }
    else if (b < 384) { in = W1; outs = W1s; K = DIM;  b -= 128; }
    else              { in = W2; outs = W2s; K = HID;  b -= 384; }

    const int e4 = (b * 256 + threadIdx.x) * 4;
    const int row = e4 / K, k = e4 % K;
    float4 v = *(const float4*)&in[e4];
    __half2 h0 = __floats2half2_rn(v.x, v.y);
    __half2 h1 = __floats2half2_rn(v.z, v.w);
    __half2 l0 = __floats2half2_rn((v.x - __half2float(h0.x)) * LO_SCALE,
                                   (v.y - __half2float(h0.y)) * LO_SCALE);
    __half2 l1 = __floats2half2_rn((v.z - __half2float(h1.x)) * LO_SCALE,
                                   (v.w - __half2float(h1.y)) * LO_SCALE);
    *(__half2*)&outs[(size_t)row * 2 * K + k]         = h0;
    *(__half2*)&outs[(size_t)row * 2 * K + k + 2]     = h1;
    *(__half2*)&outs[(size_t)row * 2 * K + K + k]     = l0;
    *(__half2*)&outs[(size_t)row * 2 * K + K + k + 2] = l1;
}

// RMODE 0: fp32 out = sum + bias, plain fp16 outs
// RMODE 2: fp32 out = aux + scale*sum
template<int RMODE>
__global__ void __launch_bounds__(256)
reduce_ep(const float* __restrict__ part, const float* __restrict__ aux,
          float scale, float* __restrict__ out, __half* __restrict__ outs)
{
    const int e4 = (blockIdx.x * 256 + threadIdx.x) * 4;
    float4 s0 = *(const float4*)&part[e4];
    float4 s1 = *(const float4*)&part[BD     + e4];
    float4 s2 = *(const float4*)&part[BD * 2 + e4];
    float4 s3 = *(const float4*)&part[BD * 3 + e4];
    float4 r;
    r.x = (s0.x + s1.x) + (s2.x + s3.x);
    r.y = (s0.y + s1.y) + (s2.y + s3.y);
    r.z = (s0.z + s1.z) + (s2.z + s3.z);
    r.w = (s0.w + s1.w) + (s2.w + s3.w);
    if (RMODE == 0) {
        float4 b = *(const float4*)&aux[e4 & (DIM - 1)];
        r.x += b.x; r.y += b.y; r.z += b.z; r.w += b.w;
        *(float4*)&out[e4] = r;
        *(__half2*)&outs[e4]     = __floats2half2_rn(r.x, r.y);
        *(__half2*)&outs[e4 + 2] = __floats2half2_rn(r.z, r.w);
    } else {
        float4 b = *(const float4*)&aux[e4];
        r.x = fmaf(scale, r.x, b.x); r.y = fmaf(scale, r.y, b.y);
        r.z = fmaf(scale, r.z, b.z); r.w = fmaf(scale, r.w, b.w);
        *(float4*)&out[e4] = r;
    }
}

extern "C" void kernel_launch(void* const* d_in, const int* in_sizes, int n_in,
                              void* d_out, int out_size)
{
    const float* y  = (const float*)d_in[0];
    const float* W1 = (const float*)d_in[1];
    const float* b1 = (const float*)d_in[2];
    const float* W2 = (const float*)d_in[3];
    const float* b2 = (const float*)d_in[4];
    float* out = (float*)d_out;

    float *pT, *pV, *pPart;
    __half *pYs, *pW1s, *pW2s, *pTs, *pPp, *pVp;
    cudaGetSymbolAddress((void**)&pT,    g_T);
    cudaGetSymbolAddress((void**)&pV,    g_V);
    cudaGetSymbolAddress((void**)&pPart, g_part);
    cudaGetSymbolAddress((void**)&pYs,   g_ys);
    cudaGetSymbolAddress((void**)&pW1s,  g_W1s);
    cudaGetSymbolAddress((void**)&pW2s,  g_W2s);
    cudaGetSymbolAddress((void**)&pTs,   g_Ts);
    cudaGetSymbolAddress((void**)&pPp,   g_Pp);
    cudaGetSymbolAddress((void**)&pVp,   g_Vp);

    dim3 gL(HID / 64, BATCH / 32, 1);   // (16,16,1) = 256 CTAs
    dim3 gS(DIM / 64, BATCH / 32, 4);   // ( 4,16,4) = 256 CTAs
    const int gR = BD / (256 * 4);      // 128

    const float c3 = 0.01f / 3.0f;

    split_all<<<640, 256>>>(y, W1, W2, pYs, pW1s, pW2s);

    // forward (fp16 split): T = tanh(y W1^T + b1);  v = T W2^T + b2
    mmagemm<MODE_TANH, 3><<<gL, 256>>>(pYs, 2 * DIM, pW1s, 2 * DIM, DIM,
                                       pT, pTs, HID, b1, nullptr);
    mmagemm<MODE_PART, 3><<<gS, 256>>>(pTs, 2 * HID, pW2s, 2 * HID, HID,
                                       pPart, nullptr, DIM, nullptr, nullptr);
    reduce_ep<0><<<gR, 256>>>(pPart, b2, 0.0f, pV, pVp);

    // out = v + 1.5 B v   (plain fp16, f16-acc corrections)
    mmagemm<MODE_MULS, 1><<<gL, 256>>>(pVp, DIM, pW1s, 2 * DIM, 0,
                                       nullptr, pPp, HID, nullptr, pT);
    mmagemm<MODE_PART, 1><<<gS, 256>>>(pPp, HID, pW2s, 2 * HID, 0,
                                       pPart, nullptr, DIM, nullptr, nullptr);
    reduce_ep<2><<<gR, 256>>>(pPart, pV, 1.5f * c3, out, nullptr);
}